// round 6
// baseline (speedup 1.0000x reference)
#include <cuda_runtime.h>
#include <cuda_bf16.h>
#include <cstdint>

#define TT 2048
#define BB 8
#define FD 768
#define HH 3
#define DH 256
#define MROWS (TT*BB)      // 16384
#define NBH (BB*HH)        // 24

// ------------------------- device scratch (static) -------------------------
__device__ __align__(16) __nv_bfloat16 g_xh[MROWS*FD], g_xl[MROWS*FD];
__device__ __align__(16) __nv_bfloat16 g_wqh[FD*FD], g_wql[FD*FD];
__device__ __align__(16) __nv_bfloat16 g_wkh[FD*FD], g_wkl[FD*FD];
__device__ __align__(16) __nv_bfloat16 g_wvh[FD*FD], g_wvl[FD*FD];
__device__ __align__(16) __nv_bfloat16 g_woh[FD*FD], g_wol[FD*FD];
__device__ __align__(16) __nv_bfloat16 g_qh[NBH*TT*DH], g_ql[NBH*TT*DH];
__device__ __align__(16) __nv_bfloat16 g_kh[NBH*TT*DH], g_kl[NBH*TT*DH];
__device__ __align__(16) __nv_bfloat16 g_vth[NBH*DH*TT], g_vtl[NBH*DH*TT];  // (BH,D,T)
__device__ __align__(16) __nv_bfloat16 g_oh[MROWS*FD], g_ol[MROWS*FD];

// ------------------------------ PTX helpers --------------------------------
__device__ __forceinline__ uint32_t smem_u32(const void* p) {
    uint32_t a;
    asm("{ .reg .u64 t; cvta.to.shared.u64 t, %1; cvt.u32.u64 %0, t; }" : "=r"(a) : "l"(p));
    return a;
}
#define CP16(dst, src) \
    asm volatile("cp.async.cg.shared.global [%0], [%1], 16;" :: "r"(dst), "l"(src) : "memory")
#define CP_COMMIT() asm volatile("cp.async.commit_group;" ::: "memory")
#define CP_WAIT0()  asm volatile("cp.async.wait_group 0;" ::: "memory")
#define CP_WAIT1()  asm volatile("cp.async.wait_group 1;" ::: "memory")

#define LDSM4(r0,r1,r2,r3,addr) \
    asm volatile("ldmatrix.sync.aligned.m8n8.x4.shared.b16 {%0,%1,%2,%3}, [%4];" \
        : "=r"(r0), "=r"(r1), "=r"(r2), "=r"(r3) : "r"(addr))

#define MMA16816(d, a, b0v, b1v) \
    asm volatile("mma.sync.aligned.m16n8k16.row.col.f32.bf16.bf16.f32 " \
        "{%0,%1,%2,%3}, {%4,%5,%6,%7}, {%8,%9}, {%0,%1,%2,%3};" \
        : "+f"((d)[0]), "+f"((d)[1]), "+f"((d)[2]), "+f"((d)[3]) \
        : "r"((a)[0]), "r"((a)[1]), "r"((a)[2]), "r"((a)[3]), "r"(b0v), "r"(b1v))

#define SWZ(o) ((uint32_t)(o) ^ ((((uint32_t)(o)) >> 3) & 0x70))

__device__ __forceinline__ void split2(float v, __nv_bfloat16& h, __nv_bfloat16& l) {
    h = __float2bfloat16(v);
    l = __float2bfloat16(v - __bfloat162float(h));
}

// ------------- split-bf16 GEMM via mma.sync, 512 threads, 256x128 -----------
#define BM 256
#define BN 128
#define BK 32
#define ROWB 80
#define MAT_A (256*ROWB)
#define MAT_B (128*ROWB)
#define OFF_AH 0
#define OFF_AL MAT_A
#define OFF_BH (2*MAT_A)
#define OFF_BL (2*MAT_A + MAT_B)
#define STAGE_BYTES (2*MAT_A + 2*MAT_B)
#define NSTAGE 3
#define SMEM_BYTES (NSTAGE*STAGE_BYTES)   // 184320

#define QSCALE 0.1803368801111204f    // 0.125 * log2(e)

// mode = blockIdx.z + mode_base: 0=Q, 1=K, 2=V(transposed out), 3=out-proj
__global__ __launch_bounds__(512, 1) void gemm_fused(
    const __nv_bfloat16* __restrict__ Ah, const __nv_bfloat16* __restrict__ Al,
    int mode_base,
    const float* __restrict__ bq, const float* __restrict__ bk,
    const float* __restrict__ bv, const float* __restrict__ bo,
    float* __restrict__ outF)
{
    extern __shared__ char smem[];
    const uint32_t sb = smem_u32(smem);

    const int tid = threadIdx.x;
    const int wid = tid >> 5, lane = tid & 31;
    const int wm = wid >> 2, wn = wid & 3;
    const int m0 = blockIdx.x * BM, n0 = blockIdx.y * BN;
    const int mode = blockIdx.z + mode_base;

    const __nv_bfloat16* Bh = mode == 0 ? g_wqh : mode == 1 ? g_wkh : mode == 2 ? g_wvh : g_woh;
    const __nv_bfloat16* Bl = mode == 0 ? g_wql : mode == 1 ? g_wkl : mode == 2 ? g_wvl : g_wol;
    const float* bias = mode == 0 ? bq : mode == 1 ? bk : mode == 2 ? bv : bo;
    const int K = FD;

    float acc[4][4][4] = {};

    const int ra0 = tid >> 2,          ca0 = tid & 3;
    const int ra1 = (tid + 512) >> 2,  ca1 = (tid + 512) & 3;
    const int rb  = tid >> 2,          cb  = tid & 3;

    auto load_stage = [&](int kb, int s) {
        const uint32_t st = sb + s * STAGE_BYTES;
        {
            size_t g = (size_t)(m0 + ra0) * K + kb * BK + ca0 * 8;
            uint32_t so = ra0 * ROWB + ca0 * 16;
            CP16(st + OFF_AH + so, Ah + g);
            CP16(st + OFF_AL + so, Al + g);
        }
        {
            size_t g = (size_t)(m0 + ra1) * K + kb * BK + ca1 * 8;
            uint32_t so = ra1 * ROWB + ca1 * 16;
            CP16(st + OFF_AH + so, Ah + g);
            CP16(st + OFF_AL + so, Al + g);
        }
        {
            size_t g = (size_t)(n0 + rb) * K + kb * BK + cb * 8;
            uint32_t so = rb * ROWB + cb * 16;
            CP16(st + OFF_BH + so, Bh + g);
            CP16(st + OFF_BL + so, Bl + g);
        }
    };

    const int NKB = K / BK;
    load_stage(0, 0); CP_COMMIT();
    load_stage(1, 1); CP_COMMIT();

    const int a_row = wm * 64 + (lane & 7) + ((lane >> 3) & 1) * 8;
    const int a_kb  = ((lane >> 4) & 1) * 16;
    const int b_row = wn * 32 + (lane & 7) + (lane >= 16 ? 8 : 0);
    const int b_kb  = ((lane >> 3) & 1) * 16;

    for (int kb = 0; kb < NKB; kb++) {
        CP_WAIT1();
        __syncthreads();
        if (kb + 2 < NKB) load_stage(kb + 2, (kb + 2) % NSTAGE);
        CP_COMMIT();

        const uint32_t st = sb + (kb % NSTAGE) * STAGE_BYTES;
        #pragma unroll
        for (int ks = 0; ks < 2; ks++) {
            uint32_t bhf[2][4], blf[2][4];
            #pragma unroll
            for (int np = 0; np < 2; np++) {
                uint32_t bo2 = (b_row + np * 16) * ROWB + b_kb + ks * 32;
                LDSM4(bhf[np][0], bhf[np][1], bhf[np][2], bhf[np][3], st + OFF_BH + bo2);
                LDSM4(blf[np][0], blf[np][1], blf[np][2], blf[np][3], st + OFF_BL + bo2);
            }
            #pragma unroll
            for (int mf = 0; mf < 4; mf++) {
                uint32_t ah[4], al[4];
                uint32_t ao = (a_row + mf * 16) * ROWB + a_kb + ks * 32;
                LDSM4(ah[0], ah[1], ah[2], ah[3], st + OFF_AH + ao);
                LDSM4(al[0], al[1], al[2], al[3], st + OFF_AL + ao);
                #pragma unroll
                for (int nf = 0; nf < 4; nf++) {
                    const int np = nf >> 1, hi = (nf & 1) * 2;
                    MMA16816(acc[mf][nf], ah, bhf[np][hi], bhf[np][hi+1]);
                    MMA16816(acc[mf][nf], ah, blf[np][hi], blf[np][hi+1]);
                    MMA16816(acc[mf][nf], al, bhf[np][hi], bhf[np][hi+1]);
                }
            }
        }
        __syncthreads();
    }

    const int mrow = m0 + wm * 64 + (lane >> 2);
    const int ncol = n0 + wn * 32 + (lane & 3) * 2;
    const float oscale = (mode == 0) ? QSCALE : 1.0f;

    #pragma unroll
    for (int mf = 0; mf < 4; mf++) {
        #pragma unroll
        for (int half = 0; half < 2; half++) {
            const int m = mrow + mf * 16 + half * 8;
            #pragma unroll
            for (int nf = 0; nf < 4; nf++) {
                const int n = ncol + nf * 8;
                float v0 = (acc[mf][nf][half * 2]     + __ldg(&bias[n]))     * oscale;
                float v1 = (acc[mf][nf][half * 2 + 1] + __ldg(&bias[n + 1])) * oscale;

                if (mode <= 1) {           // Q or K: (BH,T,D) hi/lo
                    __nv_bfloat16* oH = mode == 0 ? g_qh : g_kh;
                    __nv_bfloat16* oL = mode == 0 ? g_ql : g_kl;
                    const int t = m >> 3, b = m & 7, h = n >> 8, d = n & 255;
                    size_t o = ((size_t)(b * HH + h) * TT + t) * DH + d;
                    __nv_bfloat16 h0, l0, h1, l1; split2(v0, h0, l0); split2(v1, h1, l1);
                    __nv_bfloat162 ph; ph.x = h0; ph.y = h1;
                    __nv_bfloat162 pl; pl.x = l0; pl.y = l1;
                    *(__nv_bfloat162*)(oH + o) = ph;
                    *(__nv_bfloat162*)(oL + o) = pl;
                } else if (mode == 2) {    // V: transposed (BH,D,T) hi/lo
                    const int t = m >> 3, b = m & 7, h = n >> 8, d = n & 255;
                    size_t o = ((size_t)(b * HH + h) * DH + d) * TT + t;
                    __nv_bfloat16 h0, l0, h1, l1; split2(v0, h0, l0); split2(v1, h1, l1);
                    g_vth[o] = h0;      g_vtl[o] = l0;
                    g_vth[o + TT] = h1; g_vtl[o + TT] = l1;
                } else {                   // out projection: fp32 (T*B, F)
                    size_t o = (size_t)m * FD + n;
                    float2 f; f.x = v0; f.y = v1;
                    *(float2*)(outF + o) = f;
                }
            }
        }
    }
}

// --------------------------- fused flash attention --------------------------
// CTA: 64 q-rows of one bh; 16 kv-tiles of 128. 256 threads (4x2 warps).
// smem: Q 8x8KB | K 2bufs x 32KB (128r x 64d, h+l) | V 2bufs x 32KB | P 2x16KB | red
#define QMAT 8192
#define Q_OFF 0
#define K_OFF 65536
#define V_OFF 131072
#define P_OFF 196608
#define RMAX_OFF 229376
#define RSUM_OFF 229888
#define ATT_SMEM 230400
#define NKV (TT/128)    // 16

__global__ __launch_bounds__(256, 1) void attn_kernel()
{
    extern __shared__ char sm[];
    const uint32_t sb = smem_u32(sm);
    const int tid = threadIdx.x, lane = tid & 31, wid = tid >> 5;
    const int wm = wid & 3, wn = wid >> 2;             // 4 x 2
    const int bh = blockIdx.y, m0 = blockIdx.x * 64;

    // K chunk j of tile: 128 kv-rows x 64 d-cols, hi+lo (32KB) into buf
    auto load_k = [&](int tile, int j, int buf) {
        const uint32_t dst = sb + K_OFF + buf * 32768;
        #pragma unroll
        for (int i = 0; i < 4; i++) {
            int ci = tid + i * 256;
            int r = ci >> 3, c = ci & 7;
            size_t g = ((size_t)bh * TT + tile * 128 + r) * DH + j * 64 + c * 8;
            uint32_t so = SWZ(r * 128 + c * 16);
            CP16(dst + so,         g_kh + g);
            CP16(dst + 16384 + so, g_kl + g);
        }
    };
    // V chunk c=(p,q): buf rows 0..63 = warp0 d [p*64..), rows 64..127 = warp1 d [128+p*64..)
    // cols = t-half q (64 t)
    auto load_v = [&](int tile, int cidx, int buf) {
        const int p = cidx >> 1, q = cidx & 1;
        const uint32_t dst = sb + V_OFF + buf * 32768;
        #pragma unroll
        for (int i = 0; i < 4; i++) {
            int ci = tid + i * 256;
            int r = ci >> 3, c = ci & 7;
            int d = p * 64 + (r < 64 ? r : r + 64);
            size_t g = ((size_t)bh * DH + d) * TT + tile * 128 + q * 64 + c * 8;
            uint32_t so = SWZ(r * 128 + c * 16);
            CP16(dst + so,         g_vth + g);
            CP16(dst + 16384 + so, g_vtl + g);
        }
    };

    // prologue: Q resident (group), K j0 (group), K j1 (group)
    #pragma unroll
    for (int i = 0; i < 16; i++) {
        int ci = tid + i * 256;
        int mat = ci >> 9, w = ci & 511, r = w >> 3, c = w & 7;
        int j = mat >> 1, hl = mat & 1;
        size_t g = ((size_t)bh * TT + m0 + r) * DH + j * 64 + c * 8;
        const __nv_bfloat16* src = hl ? g_ql : g_qh;
        CP16(sb + Q_OFF + mat * QMAT + SWZ(r * 128 + c * 16), src + g);
    }
    CP_COMMIT();
    load_k(0, 0, 0); CP_COMMIT();
    load_k(0, 1, 1); CP_COMMIT();

    const int a_rl = (lane & 7) + ((lane >> 3) & 1) * 8;
    const int a_kb = ((lane >> 4) & 1) * 16;
    const int b_rl = (lane & 7) + (lane >= 16 ? 8 : 0);
    const int b_kb = ((lane >> 3) & 1) * 16;

    float oacc[16][4] = {};
    float sacc[8][4];
    float mrun0 = -1e30f, mrun1 = -1e30f, lrun0 = 0.f, lrun1 = 0.f;
    const int r0 = wm * 16 + (lane >> 2), r1 = r0 + 8;
    float* rmax = (float*)(sm + RMAX_OFF);
    float* rsum = (float*)(sm + RSUM_OFF);

    for (int tile = 0; tile < NKV; tile++) {
        #pragma unroll
        for (int f = 0; f < 8; f++) { sacc[f][0]=0.f; sacc[f][1]=0.f; sacc[f][2]=0.f; sacc[f][3]=0.f; }

        // ---- QK: 4 chunks over d ----
        #pragma unroll
        for (int j = 0; j < 4; j++) {
            CP_WAIT1(); __syncthreads();
            const uint32_t qm = sb + Q_OFF + (j * 2) * QMAT;
            const uint32_t km = sb + K_OFF + (j & 1) * 32768;
            #pragma unroll
            for (int ks = 0; ks < 4; ks++) {
                uint32_t qh[4], ql[4];
                uint32_t ao = SWZ((wm * 16 + a_rl) * 128 + a_kb + ks * 32);
                LDSM4(qh[0], qh[1], qh[2], qh[3], qm + ao);
                LDSM4(ql[0], ql[1], ql[2], ql[3], qm + QMAT + ao);
                #pragma unroll
                for (int g16 = 0; g16 < 4; g16++) {
                    uint32_t kh[4], kl[4];
                    uint32_t bo = SWZ((wn * 64 + g16 * 16 + b_rl) * 128 + b_kb + ks * 32);
                    LDSM4(kh[0], kh[1], kh[2], kh[3], km + bo);
                    LDSM4(kl[0], kl[1], kl[2], kl[3], km + 16384 + bo);
                    const int f = g16 * 2;
                    MMA16816(sacc[f],   qh, kh[0], kh[1]);
                    MMA16816(sacc[f],   qh, kl[0], kl[1]);
                    MMA16816(sacc[f],   ql, kh[0], kh[1]);
                    MMA16816(sacc[f+1], qh, kh[2], kh[3]);
                    MMA16816(sacc[f+1], qh, kl[2], kl[3]);
                    MMA16816(sacc[f+1], ql, kh[2], kh[3]);
                }
            }
            __syncthreads();
            if (j < 2) load_k(tile, j + 2, j & 1);
            else       load_v(tile, j - 2, j & 1);
            CP_COMMIT();
        }

        // ---- online softmax (scores already in log2 units) ----
        float mx0 = -1e30f, mx1 = -1e30f;
        #pragma unroll
        for (int f = 0; f < 8; f++) {
            mx0 = fmaxf(mx0, fmaxf(sacc[f][0], sacc[f][1]));
            mx1 = fmaxf(mx1, fmaxf(sacc[f][2], sacc[f][3]));
        }
        mx0 = fmaxf(mx0, __shfl_xor_sync(0xffffffffu, mx0, 1));
        mx0 = fmaxf(mx0, __shfl_xor_sync(0xffffffffu, mx0, 2));
        mx1 = fmaxf(mx1, __shfl_xor_sync(0xffffffffu, mx1, 1));
        mx1 = fmaxf(mx1, __shfl_xor_sync(0xffffffffu, mx1, 2));
        if ((lane & 3) == 0) { rmax[wn * 64 + r0] = mx0; rmax[wn * 64 + r1] = mx1; }
        __syncthreads();

        float mn0 = fmaxf(mrun0, fmaxf(rmax[r0], rmax[64 + r0]));
        float mn1 = fmaxf(mrun1, fmaxf(rmax[r1], rmax[64 + r1]));
        float a0 = exp2f(mrun0 - mn0), a1 = exp2f(mrun1 - mn1);
        mrun0 = mn0; mrun1 = mn1;

        float s0 = 0.f, s1 = 0.f;
        #pragma unroll
        for (int f = 0; f < 8; f++) {
            sacc[f][0] = exp2f(sacc[f][0] - mn0);
            sacc[f][1] = exp2f(sacc[f][1] - mn0);
            sacc[f][2] = exp2f(sacc[f][2] - mn1);
            sacc[f][3] = exp2f(sacc[f][3] - mn1);
            s0 += sacc[f][0] + sacc[f][1];
            s1 += sacc[f][2] + sacc[f][3];
        }
        s0 += __shfl_xor_sync(0xffffffffu, s0, 1);
        s0 += __shfl_xor_sync(0xffffffffu, s0, 2);
        s1 += __shfl_xor_sync(0xffffffffu, s1, 1);
        s1 += __shfl_xor_sync(0xffffffffu, s1, 2);
        if ((lane & 3) == 0) { rsum[wn * 64 + r0] = s0; rsum[wn * 64 + r1] = s1; }

        #pragma unroll
        for (int f = 0; f < 16; f++) {
            oacc[f][0] *= a0; oacc[f][1] *= a0;
            oacc[f][2] *= a1; oacc[f][3] *= a1;
        }

        // P -> smem (warp wn owns t-half mat wn)
        {
            const uint32_t pmw = sb + P_OFF + wn * 16384;
            #pragma unroll
            for (int f = 0; f < 8; f++) {
                int cl = f * 8 + (lane & 3) * 2;
                __nv_bfloat16 h0, l0, h1, l1;
                split2(sacc[f][0], h0, l0); split2(sacc[f][1], h1, l1);
                __nv_bfloat162 ph; ph.x = h0; ph.y = h1;
                __nv_bfloat162 pl; pl.x = l0; pl.y = l1;
                uint32_t off = SWZ(r0 * 128 + cl * 2);
                *(__nv_bfloat162*)(sm + (pmw - sb) + off)        = ph;
                *(__nv_bfloat162*)(sm + (pmw - sb) + 8192 + off) = pl;
                split2(sacc[f][2], h0, l0); split2(sacc[f][3], h1, l1);
                ph.x = h0; ph.y = h1; pl.x = l0; pl.y = l1;
                off = SWZ(r1 * 128 + cl * 2);
                *(__nv_bfloat162*)(sm + (pmw - sb) + off)        = ph;
                *(__nv_bfloat162*)(sm + (pmw - sb) + 8192 + off) = pl;
            }
        }
        __syncthreads();

        lrun0 = lrun0 * a0 + rsum[r0] + rsum[64 + r0];
        lrun1 = lrun1 * a1 + rsum[r1] + rsum[64 + r1];

        // ---- AV: 4 phases (p = d-half, q = t-half) ----
        #pragma unroll
        for (int c = 0; c < 4; c++) {
            if (tile == NKV - 1 && c >= 2) { CP_WAIT0(); } else { CP_WAIT1(); }
            __syncthreads();
            const int p = c >> 1, q = c & 1;
            const uint32_t vm = sb + V_OFF + (c & 1) * 32768;
            const uint32_t pm = sb + P_OFF + q * 16384;
            #pragma unroll
            for (int ks = 0; ks < 4; ks++) {
                uint32_t ph[4], pl[4];
                uint32_t ao = SWZ((wm * 16 + a_rl) * 128 + a_kb + ks * 32);
                LDSM4(ph[0], ph[1], ph[2], ph[3], pm + ao);
                LDSM4(pl[0], pl[1], pl[2], pl[3], pm + 8192 + ao);
                #pragma unroll
                for (int g16 = 0; g16 < 4; g16++) {
                    uint32_t vh[4], vl[4];
                    uint32_t bo = SWZ((wn * 64 + g16 * 16 + b_rl) * 128 + b_kb + ks * 32);
                    LDSM4(vh[0], vh[1], vh[2], vh[3], vm + bo);
                    LDSM4(vl[0], vl[1], vl[2], vl[3], vm + 16384 + bo);
                    const int f = p * 8 + g16 * 2;
                    MMA16816(oacc[f],   ph, vh[0], vh[1]);
                    MMA16816(oacc[f],   ph, vl[0], vl[1]);
                    MMA16816(oacc[f],   pl, vh[0], vh[1]);
                    MMA16816(oacc[f+1], ph, vh[2], vh[3]);
                    MMA16816(oacc[f+1], ph, vl[2], vl[3]);
                    MMA16816(oacc[f+1], pl, vh[2], vh[3]);
                }
            }
            __syncthreads();
            if (c < 2) { load_v(tile, c + 2, c & 1); CP_COMMIT(); }
            else if (tile + 1 < NKV) { load_k(tile + 1, c - 2, c & 1); CP_COMMIT(); }
        }
    }

    // ---- epilogue ----
    const int bb = bh / HH, hh = bh % HH;
    const float inv0 = 1.f / lrun0, inv1 = 1.f / lrun1;
    #pragma unroll
    for (int idx = 0; idx < 16; idx++) {
        const int p = idx >> 3, f = idx & 7;
        const int d = wn * 128 + p * 64 + f * 8 + (lane & 3) * 2;
        {
            int t = m0 + r0;
            float v0 = oacc[idx][0] * inv0, v1 = oacc[idx][1] * inv0;
            size_t o = ((size_t)t * BB + bb) * FD + hh * DH + d;
            __nv_bfloat16 h0, l0, h1, l1; split2(v0, h0, l0); split2(v1, h1, l1);
            __nv_bfloat162 ph; ph.x = h0; ph.y = h1;
            __nv_bfloat162 pl; pl.x = l0; pl.y = l1;
            *(__nv_bfloat162*)(g_oh + o) = ph;
            *(__nv_bfloat162*)(g_ol + o) = pl;
        }
        {
            int t = m0 + r1;
            float v0 = oacc[idx][2] * inv1, v1 = oacc[idx][3] * inv1;
            size_t o = ((size_t)t * BB + bb) * FD + hh * DH + d;
            __nv_bfloat16 h0, l0, h1, l1; split2(v0, h0, l0); split2(v1, h1, l1);
            __nv_bfloat162 ph; ph.x = h0; ph.y = h1;
            __nv_bfloat162 pl; pl.x = l0; pl.y = l1;
            *(__nv_bfloat162*)(g_oh + o) = ph;
            *(__nv_bfloat162*)(g_ol + o) = pl;
        }
    }
}

// ------------------------------ helper kernels ------------------------------
__global__ __launch_bounds__(256) void split_kernel(
    const float* __restrict__ in, __nv_bfloat16* __restrict__ h,
    __nv_bfloat16* __restrict__ l, int n4)
{
    int i = blockIdx.x * 256 + threadIdx.x;
    if (i >= n4) return;
    float4 v = *(const float4*)(in + (size_t)i * 4);
    __nv_bfloat16 h0,l0,h1,l1,h2,l2,h3,l3;
    split2(v.x,h0,l0); split2(v.y,h1,l1); split2(v.z,h2,l2); split2(v.w,h3,l3);
    __nv_bfloat162 a; a.x=h0; a.y=h1; __nv_bfloat162 b; b.x=h2; b.y=h3;
    __nv_bfloat162 c; c.x=l0; c.y=l1; __nv_bfloat162 d; d.x=l2; d.y=l3;
    *(__nv_bfloat162*)(h + (size_t)i*4)     = a;
    *(__nv_bfloat162*)(h + (size_t)i*4 + 2) = b;
    *(__nv_bfloat162*)(l + (size_t)i*4)     = c;
    *(__nv_bfloat162*)(l + (size_t)i*4 + 2) = d;
}

__global__ __launch_bounds__(256) void split_w_kernel(
    const float* __restrict__ w0, const float* __restrict__ w1,
    const float* __restrict__ w2, const float* __restrict__ w3)
{
    const int which = blockIdx.y;
    const float* in = which == 0 ? w0 : which == 1 ? w1 : which == 2 ? w2 : w3;
    __nv_bfloat16* h = which == 0 ? g_wqh : which == 1 ? g_wkh : which == 2 ? g_wvh : g_woh;
    __nv_bfloat16* l = which == 0 ? g_wql : which == 1 ? g_wkl : which == 2 ? g_wvl : g_wol;
    int i = blockIdx.x * 256 + threadIdx.x;
    if (i >= FD*FD/4) return;
    float4 v = *(const float4*)(in + (size_t)i * 4);
    __nv_bfloat16 a0,b0,a1,b1,a2,b2,a3,b3;
    split2(v.x,a0,b0); split2(v.y,a1,b1); split2(v.z,a2,b2); split2(v.w,a3,b3);
    __nv_bfloat162 p; p.x=a0; p.y=a1; __nv_bfloat162 q; q.x=a2; q.y=a3;
    __nv_bfloat162 r; r.x=b0; r.y=b1; __nv_bfloat162 s; s.x=b2; s.y=b3;
    *(__nv_bfloat162*)(h + (size_t)i*4)     = p;
    *(__nv_bfloat162*)(h + (size_t)i*4 + 2) = q;
    *(__nv_bfloat162*)(l + (size_t)i*4)     = r;
    *(__nv_bfloat162*)(l + (size_t)i*4 + 2) = s;
}

// --------------------------------- launch ----------------------------------
extern "C" void kernel_launch(void* const* d_in, const int* in_sizes, int n_in,
                              void* d_out, int out_size)
{
    const float* x  = (const float*)d_in[0];
    const float* Wq = (const float*)d_in[1];
    const float* bq = (const float*)d_in[2];
    const float* Wk = (const float*)d_in[3];
    const float* bk = (const float*)d_in[4];
    const float* Wv = (const float*)d_in[5];
    const float* bv = (const float*)d_in[6];
    const float* Wo = (const float*)d_in[7];
    const float* bo = (const float*)d_in[8];
    float* out = (float*)d_out;

    cudaFuncSetAttribute(gemm_fused,  cudaFuncAttributeMaxDynamicSharedMemorySize, SMEM_BYTES);
    cudaFuncSetAttribute(attn_kernel, cudaFuncAttributeMaxDynamicSharedMemorySize, ATT_SMEM);

    __nv_bfloat16 *xh, *xl, *oh, *ol;
    cudaGetSymbolAddress((void**)&xh, g_xh);  cudaGetSymbolAddress((void**)&xl, g_xl);
    cudaGetSymbolAddress((void**)&oh, g_oh);  cudaGetSymbolAddress((void**)&ol, g_ol);

    // 0: x split
    split_kernel<<<(MROWS*FD/4 + 255)/256, 256>>>(x, xh, xl, MROWS*FD/4);
    // 1: W splits
    dim3 gW((FD*FD/4 + 255)/256, 4);
    split_w_kernel<<<gW, 256>>>(Wq, Wk, Wv, Wo);
    // 2: fused QKV projection (z = 0,1,2)
    dim3 gQKV(MROWS/BM, FD/BN, 3);
    gemm_fused<<<gQKV, 512, SMEM_BYTES>>>(xh, xl, 0, bq, bk, bv, bo, out);
    // 3: fused flash attention
    dim3 gA(TT/64, NBH);
    attn_kernel<<<gA, 256, ATT_SMEM>>>();
    // 4: output projection (mode 3)
    dim3 gO(MROWS/BM, FD/BN, 1);
    gemm_fused<<<gO, 512, SMEM_BYTES>>>(oh, ol, 3, bq, bk, bv, bo, out);
}

// round 7
// speedup vs baseline: 1.1403x; 1.1403x over previous
#include <cuda_runtime.h>
#include <cuda_bf16.h>
#include <cstdint>

#define TT 2048
#define BB 8
#define FD 768
#define HH 3
#define DH 256
#define MROWS (TT*BB)      // 16384
#define NBH (BB*HH)        // 24

// ------------------------- device scratch (static) -------------------------
__device__ __align__(16) __nv_bfloat16 g_xh[MROWS*FD], g_xl[MROWS*FD];
__device__ __align__(16) __nv_bfloat16 g_wqh[FD*FD], g_wql[FD*FD];
__device__ __align__(16) __nv_bfloat16 g_wkh[FD*FD], g_wkl[FD*FD];
__device__ __align__(16) __nv_bfloat16 g_wvh[FD*FD], g_wvl[FD*FD];
__device__ __align__(16) __nv_bfloat16 g_woh[FD*FD], g_wol[FD*FD];
__device__ __align__(16) __nv_bfloat16 g_qh[NBH*TT*DH], g_ql[NBH*TT*DH];
__device__ __align__(16) __nv_bfloat16 g_kh[NBH*TT*DH], g_kl[NBH*TT*DH];
__device__ __align__(16) __nv_bfloat16 g_vh[NBH*TT*DH], g_vl[NBH*TT*DH];   // (BH,T,D)
__device__ __align__(16) __nv_bfloat16 g_oh[MROWS*FD], g_ol[MROWS*FD];

// ------------------------------ PTX helpers --------------------------------
__device__ __forceinline__ uint32_t smem_u32(const void* p) {
    uint32_t a;
    asm("{ .reg .u64 t; cvta.to.shared.u64 t, %1; cvt.u32.u64 %0, t; }" : "=r"(a) : "l"(p));
    return a;
}
#define CP16(dst, src) \
    asm volatile("cp.async.cg.shared.global [%0], [%1], 16;" :: "r"(dst), "l"(src) : "memory")
#define CP_COMMIT() asm volatile("cp.async.commit_group;" ::: "memory")
#define CP_WAIT1()  asm volatile("cp.async.wait_group 1;" ::: "memory")

#define LDSM4(r0,r1,r2,r3,addr) \
    asm volatile("ldmatrix.sync.aligned.m8n8.x4.shared.b16 {%0,%1,%2,%3}, [%4];" \
        : "=r"(r0), "=r"(r1), "=r"(r2), "=r"(r3) : "r"(addr))
#define LDSM4T(r0,r1,r2,r3,addr) \
    asm volatile("ldmatrix.sync.aligned.m8n8.x4.trans.shared.b16 {%0,%1,%2,%3}, [%4];" \
        : "=r"(r0), "=r"(r1), "=r"(r2), "=r"(r3) : "r"(addr))

#define MMA16816(d, a, b0v, b1v) \
    asm volatile("mma.sync.aligned.m16n8k16.row.col.f32.bf16.bf16.f32 " \
        "{%0,%1,%2,%3}, {%4,%5,%6,%7}, {%8,%9}, {%0,%1,%2,%3};" \
        : "+f"((d)[0]), "+f"((d)[1]), "+f"((d)[2]), "+f"((d)[3]) \
        : "r"((a)[0]), "r"((a)[1]), "r"((a)[2]), "r"((a)[3]), "r"(b0v), "r"(b1v))

#define SWZ(o) ((uint32_t)(o) ^ ((((uint32_t)(o)) >> 3) & 0x70))

__device__ __forceinline__ void split2(float v, __nv_bfloat16& h, __nv_bfloat16& l) {
    h = __float2bfloat16(v);
    l = __float2bfloat16(v - __bfloat162float(h));
}

// ------------- split-bf16 GEMM via mma.sync, 512 threads, 256x128 -----------
#define BM 256
#define BN 128
#define BK 32
#define ROWB 80
#define MAT_A (256*ROWB)
#define MAT_B (128*ROWB)
#define OFF_AH 0
#define OFF_AL MAT_A
#define OFF_BH (2*MAT_A)
#define OFF_BL (2*MAT_A + MAT_B)
#define STAGE_BYTES (2*MAT_A + 2*MAT_B)
#define NSTAGE 3
#define SMEM_BYTES (NSTAGE*STAGE_BYTES)   // 184320

#define QSCALE 0.1803368801111204f    // 0.125 * log2(e)

// mode = blockIdx.z + mode_base: 0=Q, 1=K, 2=V, 3=out-proj
__global__ __launch_bounds__(512, 1) void gemm_fused(
    const __nv_bfloat16* __restrict__ Ah, const __nv_bfloat16* __restrict__ Al,
    int mode_base,
    const float* __restrict__ bq, const float* __restrict__ bk,
    const float* __restrict__ bv, const float* __restrict__ bo,
    float* __restrict__ outF)
{
    extern __shared__ char smem[];
    const uint32_t sb = smem_u32(smem);

    const int tid = threadIdx.x;
    const int wid = tid >> 5, lane = tid & 31;
    const int wm = wid >> 2, wn = wid & 3;
    const int m0 = blockIdx.x * BM, n0 = blockIdx.y * BN;
    const int mode = blockIdx.z + mode_base;

    const __nv_bfloat16* Bh = mode == 0 ? g_wqh : mode == 1 ? g_wkh : mode == 2 ? g_wvh : g_woh;
    const __nv_bfloat16* Bl = mode == 0 ? g_wql : mode == 1 ? g_wkl : mode == 2 ? g_wvl : g_wol;
    const float* bias = mode == 0 ? bq : mode == 1 ? bk : mode == 2 ? bv : bo;
    const int K = FD;

    float acc[4][4][4] = {};

    const int ra0 = tid >> 2,          ca0 = tid & 3;
    const int ra1 = (tid + 512) >> 2,  ca1 = (tid + 512) & 3;
    const int rb  = tid >> 2,          cb  = tid & 3;

    auto load_stage = [&](int kb, int s) {
        const uint32_t st = sb + s * STAGE_BYTES;
        {
            size_t g = (size_t)(m0 + ra0) * K + kb * BK + ca0 * 8;
            uint32_t so = ra0 * ROWB + ca0 * 16;
            CP16(st + OFF_AH + so, Ah + g);
            CP16(st + OFF_AL + so, Al + g);
        }
        {
            size_t g = (size_t)(m0 + ra1) * K + kb * BK + ca1 * 8;
            uint32_t so = ra1 * ROWB + ca1 * 16;
            CP16(st + OFF_AH + so, Ah + g);
            CP16(st + OFF_AL + so, Al + g);
        }
        {
            size_t g = (size_t)(n0 + rb) * K + kb * BK + cb * 8;
            uint32_t so = rb * ROWB + cb * 16;
            CP16(st + OFF_BH + so, Bh + g);
            CP16(st + OFF_BL + so, Bl + g);
        }
    };

    const int NKB = K / BK;
    load_stage(0, 0); CP_COMMIT();
    load_stage(1, 1); CP_COMMIT();

    const int a_row = wm * 64 + (lane & 7) + ((lane >> 3) & 1) * 8;
    const int a_kb  = ((lane >> 4) & 1) * 16;
    const int b_row = wn * 32 + (lane & 7) + (lane >= 16 ? 8 : 0);
    const int b_kb  = ((lane >> 3) & 1) * 16;

    for (int kb = 0; kb < NKB; kb++) {
        CP_WAIT1();
        __syncthreads();
        if (kb + 2 < NKB) load_stage(kb + 2, (kb + 2) % NSTAGE);
        CP_COMMIT();

        const uint32_t st = sb + (kb % NSTAGE) * STAGE_BYTES;
        #pragma unroll
        for (int ks = 0; ks < 2; ks++) {
            uint32_t bhf[2][4], blf[2][4];
            #pragma unroll
            for (int np = 0; np < 2; np++) {
                uint32_t bo2 = (b_row + np * 16) * ROWB + b_kb + ks * 32;
                LDSM4(bhf[np][0], bhf[np][1], bhf[np][2], bhf[np][3], st + OFF_BH + bo2);
                LDSM4(blf[np][0], blf[np][1], blf[np][2], blf[np][3], st + OFF_BL + bo2);
            }
            #pragma unroll
            for (int mf = 0; mf < 4; mf++) {
                uint32_t ah[4], al[4];
                uint32_t ao = (a_row + mf * 16) * ROWB + a_kb + ks * 32;
                LDSM4(ah[0], ah[1], ah[2], ah[3], st + OFF_AH + ao);
                LDSM4(al[0], al[1], al[2], al[3], st + OFF_AL + ao);
                #pragma unroll
                for (int np = 0; np < 2; np++) {
                    MMA16816(acc[mf][np*2],   ah, bhf[np][0], bhf[np][1]);
                    MMA16816(acc[mf][np*2+1], ah, bhf[np][2], bhf[np][3]);
                    MMA16816(acc[mf][np*2],   ah, blf[np][0], blf[np][1]);
                    MMA16816(acc[mf][np*2+1], ah, blf[np][2], blf[np][3]);
                    MMA16816(acc[mf][np*2],   al, bhf[np][0], bhf[np][1]);
                    MMA16816(acc[mf][np*2+1], al, bhf[np][2], bhf[np][3]);
                }
            }
        }
        __syncthreads();
    }

    const int mrow = m0 + wm * 64 + (lane >> 2);
    const int ncol = n0 + wn * 32 + (lane & 3) * 2;
    const float oscale = (mode == 0) ? QSCALE : 1.0f;

    #pragma unroll
    for (int mf = 0; mf < 4; mf++) {
        #pragma unroll
        for (int half = 0; half < 2; half++) {
            const int m = mrow + mf * 16 + half * 8;
            #pragma unroll
            for (int nf = 0; nf < 4; nf++) {
                // remap: acc[mf][np*2+e] covers n = ncol + (np*2+e)*8? keep original nf order
                const int n = ncol + nf * 8;
                float v0 = (acc[mf][nf][half * 2]     + __ldg(&bias[n]))     * oscale;
                float v1 = (acc[mf][nf][half * 2 + 1] + __ldg(&bias[n + 1])) * oscale;

                if (mode <= 2) {           // Q/K/V: (BH,T,D) hi/lo, coalesced
                    __nv_bfloat16* oH = mode == 0 ? g_qh : mode == 1 ? g_kh : g_vh;
                    __nv_bfloat16* oL = mode == 0 ? g_ql : mode == 1 ? g_kl : g_vl;
                    const int t = m >> 3, b = m & 7, h = n >> 8, d = n & 255;
                    size_t o = ((size_t)(b * HH + h) * TT + t) * DH + d;
                    __nv_bfloat16 h0, l0, h1, l1; split2(v0, h0, l0); split2(v1, h1, l1);
                    __nv_bfloat162 ph; ph.x = h0; ph.y = h1;
                    __nv_bfloat162 pl; pl.x = l0; pl.y = l1;
                    *(__nv_bfloat162*)(oH + o) = ph;
                    *(__nv_bfloat162*)(oL + o) = pl;
                } else {                   // out projection: fp32 (T*B, F)
                    size_t o = (size_t)m * FD + n;
                    float2 f; f.x = v0; f.y = v1;
                    *(float2*)(outF + o) = f;
                }
            }
        }
    }
}

// --------------------------- fused flash attention --------------------------
// CTA: 64 q-rows of one bh; 16 kv-tiles of 128 t. 256 threads (4m x 2n warps).
// Two 64KB ping-pong buffers hold [128 t][128 d] hi/lo chunks (K or V).
// Per tile: 2 QK phases (d-halves) + softmax + 2 AV phases (d-halves).
// Buffer mats: (dhalf, hl) at buf + dhalf*32768 + hl*16384, each [128r][64c] SW128.
#define QMAT 8192
#define Q_OFF 0
#define B0_OFF 65536
#define B1_OFF 131072
#define P_OFF 196608
#define RMAX_OFF 229376
#define RSUM_OFF 229888
#define ATT_SMEM 230400
#define NKV (TT/128)    // 16

__global__ __launch_bounds__(256, 1) void attn_kernel()
{
    extern __shared__ char sm[];
    const uint32_t sb = smem_u32(sm);
    const int tid = threadIdx.x, lane = tid & 31, wid = tid >> 5;
    const int wm = wid & 3, wn = wid >> 2;             // 4 x 2
    const int bh = blockIdx.y, m0 = blockIdx.x * 64;

    // load a [128 t][128 d] hi/lo chunk (c = d-half of DH) from (BH,T,D) src
    auto load_kv = [&](const __nv_bfloat16* __restrict__ srcH,
                       const __nv_bfloat16* __restrict__ srcL,
                       int tile, int c, uint32_t bufoff) {
        #pragma unroll
        for (int dh = 0; dh < 2; dh++) {
            #pragma unroll
            for (int i = 0; i < 4; i++) {
                int ci = tid + i * 256;
                int r = ci >> 3, cc = ci & 7;
                size_t g = ((size_t)bh * TT + tile * 128 + r) * DH + c * 128 + dh * 64 + cc * 8;
                uint32_t so = SWZ(r * 128 + cc * 16);
                CP16(sb + bufoff + dh * 32768 + so,         srcH + g);
                CP16(sb + bufoff + dh * 32768 + 16384 + so, srcL + g);
            }
        }
    };

    // prologue: Q resident (+ K chunk 0 in group 0), K chunk 1 in group 1
    #pragma unroll
    for (int i = 0; i < 16; i++) {
        int ci = tid + i * 256;
        int mat = ci >> 9, w = ci & 511, r = w >> 3, c = w & 7;
        int j = mat >> 1, hl = mat & 1;
        size_t g = ((size_t)bh * TT + m0 + r) * DH + j * 64 + c * 8;
        const __nv_bfloat16* src = hl ? g_ql : g_qh;
        CP16(sb + Q_OFF + mat * QMAT + SWZ(r * 128 + c * 16), src + g);
    }
    load_kv(g_kh, g_kl, 0, 0, B0_OFF); CP_COMMIT();
    load_kv(g_kh, g_kl, 0, 1, B1_OFF); CP_COMMIT();

    const int a_rl = (lane & 7) + ((lane >> 3) & 1) * 8;
    const int a_kb = ((lane >> 4) & 1) * 16;
    const int b_rl = (lane & 7) + (lane >= 16 ? 8 : 0);
    const int b_kb = ((lane >> 3) & 1) * 16;
    // ldmatrix.trans lane addressing for V ([t][d] -> B[k=t][n=d])
    const int v_rl = (lane & 7) + ((lane >> 3) & 1) * 8;
    const int v_cb = ((lane >> 4) & 1) * 16;

    float oacc[16][4] = {};
    float sacc[8][4];
    float mrun0 = -1e30f, mrun1 = -1e30f, lrun0 = 0.f, lrun1 = 0.f;
    const int r0 = wm * 16 + (lane >> 2), r1 = r0 + 8;
    float* rmax = (float*)(sm + RMAX_OFF);
    float* rsum = (float*)(sm + RSUM_OFF);

    for (int tile = 0; tile < NKV; tile++) {
        #pragma unroll
        for (int f = 0; f < 8; f++) { sacc[f][0]=0.f; sacc[f][1]=0.f; sacc[f][2]=0.f; sacc[f][3]=0.f; }

        // ---- QK: 2 phases over d-halves ----
        #pragma unroll
        for (int c = 0; c < 2; c++) {
            CP_WAIT1(); __syncthreads();
            const uint32_t kb_buf = sb + (c ? B1_OFF : B0_OFF);
            #pragma unroll
            for (int ks = 0; ks < 8; ks++) {
                const uint32_t qm = sb + Q_OFF + (c * 2 + (ks >> 2)) * 16384;
                const uint32_t km = kb_buf + (ks >> 2) * 32768;
                uint32_t ao = SWZ((wm * 16 + a_rl) * 128 + (ks & 3) * 32 + a_kb);
                uint32_t qh[4], ql[4];
                LDSM4(qh[0], qh[1], qh[2], qh[3], qm + ao);
                LDSM4(ql[0], ql[1], ql[2], ql[3], qm + 8192 + ao);
                #pragma unroll
                for (int g16 = 0; g16 < 4; g16++) {
                    uint32_t bo = SWZ((wn * 64 + g16 * 16 + b_rl) * 128 + (ks & 3) * 32 + b_kb);
                    uint32_t kh[4], kl[4];
                    LDSM4(kh[0], kh[1], kh[2], kh[3], km + bo);
                    LDSM4(kl[0], kl[1], kl[2], kl[3], km + 16384 + bo);
                    const int f = g16 * 2;
                    MMA16816(sacc[f],   qh, kh[0], kh[1]);
                    MMA16816(sacc[f+1], qh, kh[2], kh[3]);
                    MMA16816(sacc[f],   qh, kl[0], kl[1]);
                    MMA16816(sacc[f+1], qh, kl[2], kl[3]);
                    MMA16816(sacc[f],   ql, kh[0], kh[1]);
                    MMA16816(sacc[f+1], ql, kh[2], kh[3]);
                }
            }
            __syncthreads();
            load_kv(g_vh, g_vl, tile, c, c ? B1_OFF : B0_OFF);   // V chunk c into same buf
            CP_COMMIT();
        }

        // ---- online softmax (scores in log2 units via folded QSCALE) ----
        float mx0 = -1e30f, mx1 = -1e30f;
        #pragma unroll
        for (int f = 0; f < 8; f++) {
            mx0 = fmaxf(mx0, fmaxf(sacc[f][0], sacc[f][1]));
            mx1 = fmaxf(mx1, fmaxf(sacc[f][2], sacc[f][3]));
        }
        mx0 = fmaxf(mx0, __shfl_xor_sync(0xffffffffu, mx0, 1));
        mx0 = fmaxf(mx0, __shfl_xor_sync(0xffffffffu, mx0, 2));
        mx1 = fmaxf(mx1, __shfl_xor_sync(0xffffffffu, mx1, 1));
        mx1 = fmaxf(mx1, __shfl_xor_sync(0xffffffffu, mx1, 2));
        if ((lane & 3) == 0) { rmax[wn * 64 + r0] = mx0; rmax[wn * 64 + r1] = mx1; }
        __syncthreads();

        float mn0 = fmaxf(mrun0, fmaxf(rmax[r0], rmax[64 + r0]));
        float mn1 = fmaxf(mrun1, fmaxf(rmax[r1], rmax[64 + r1]));
        float a0 = exp2f(mrun0 - mn0), a1 = exp2f(mrun1 - mn1);
        mrun0 = mn0; mrun1 = mn1;

        float s0 = 0.f, s1 = 0.f;
        #pragma unroll
        for (int f = 0; f < 8; f++) {
            sacc[f][0] = exp2f(sacc[f][0] - mn0);
            sacc[f][1] = exp2f(sacc[f][1] - mn0);
            sacc[f][2] = exp2f(sacc[f][2] - mn1);
            sacc[f][3] = exp2f(sacc[f][3] - mn1);
            s0 += sacc[f][0] + sacc[f][1];
            s1 += sacc[f][2] + sacc[f][3];
        }
        s0 += __shfl_xor_sync(0xffffffffu, s0, 1);
        s0 += __shfl_xor_sync(0xffffffffu, s0, 2);
        s1 += __shfl_xor_sync(0xffffffffu, s1, 1);
        s1 += __shfl_xor_sync(0xffffffffu, s1, 2);
        if ((lane & 3) == 0) { rsum[wn * 64 + r0] = s0; rsum[wn * 64 + r1] = s1; }

        #pragma unroll
        for (int f = 0; f < 16; f++) {
            oacc[f][0] *= a0; oacc[f][1] *= a0;
            oacc[f][2] *= a1; oacc[f][3] *= a1;
        }

        // P -> smem: warp wn's sacc covers t-local [wn*64, wn*64+64) = mat wn
        {
            const uint32_t pmo = P_OFF + wn * 16384;
            #pragma unroll
            for (int f = 0; f < 8; f++) {
                int cl = f * 8 + (lane & 3) * 2;
                __nv_bfloat16 h0, l0, h1, l1;
                split2(sacc[f][0], h0, l0); split2(sacc[f][1], h1, l1);
                __nv_bfloat162 ph; ph.x = h0; ph.y = h1;
                __nv_bfloat162 pl; pl.x = l0; pl.y = l1;
                uint32_t off = SWZ(r0 * 128 + cl * 2);
                *(__nv_bfloat162*)(sm + pmo + off)        = ph;
                *(__nv_bfloat162*)(sm + pmo + 8192 + off) = pl;
                split2(sacc[f][2], h0, l0); split2(sacc[f][3], h1, l1);
                ph.x = h0; ph.y = h1; pl.x = l0; pl.y = l1;
                off = SWZ(r1 * 128 + cl * 2);
                *(__nv_bfloat162*)(sm + pmo + off)        = ph;
                *(__nv_bfloat162*)(sm + pmo + 8192 + off) = pl;
            }
        }
        __syncthreads();

        lrun0 = lrun0 * a0 + rsum[r0] + rsum[64 + r0];
        lrun1 = lrun1 * a1 + rsum[r1] + rsum[64 + r1];

        // ---- AV: 2 phases over d-halves (V via ldmatrix.trans) ----
        #pragma unroll
        for (int c = 0; c < 2; c++) {
            CP_WAIT1(); __syncthreads();
            const uint32_t v_buf = sb + (c ? B1_OFF : B0_OFF) + wn * 32768;  // dhalf = wn
            #pragma unroll
            for (int ks = 0; ks < 8; ks++) {
                const uint32_t pm = sb + P_OFF + (ks >> 2) * 16384;
                uint32_t ao = SWZ((wm * 16 + a_rl) * 128 + (ks & 3) * 32 + a_kb);
                uint32_t ph[4], pl[4];
                LDSM4(ph[0], ph[1], ph[2], ph[3], pm + ao);
                LDSM4(pl[0], pl[1], pl[2], pl[3], pm + 8192 + ao);
                const uint32_t vrow = ks * 16 + v_rl;
                #pragma unroll
                for (int g16 = 0; g16 < 4; g16++) {
                    uint32_t bo = SWZ(vrow * 128 + g16 * 32 + v_cb);
                    uint32_t vh[4], vl[4];
                    LDSM4T(vh[0], vh[1], vh[2], vh[3], v_buf + bo);
                    LDSM4T(vl[0], vl[1], vl[2], vl[3], v_buf + 16384 + bo);
                    const int f = c * 8 + g16 * 2;
                    MMA16816(oacc[f],   ph, vh[0], vh[1]);
                    MMA16816(oacc[f+1], ph, vh[2], vh[3]);
                    MMA16816(oacc[f],   ph, vl[0], vl[1]);
                    MMA16816(oacc[f+1], ph, vl[2], vl[3]);
                    MMA16816(oacc[f],   pl, vh[0], vh[1]);
                    MMA16816(oacc[f+1], pl, vh[2], vh[3]);
                }
            }
            __syncthreads();
            if (tile + 1 < NKV) load_kv(g_kh, g_kl, tile + 1, c, c ? B1_OFF : B0_OFF);
            CP_COMMIT();
        }
    }

    // ---- epilogue: normalize + write hi/lo for output projection ----
    const int bb = bh / HH, hh = bh % HH;
    const float inv0 = 1.f / lrun0, inv1 = 1.f / lrun1;
    #pragma unroll
    for (int idx = 0; idx < 16; idx++) {
        const int c = idx >> 3, g16 = (idx & 7) >> 1, e = idx & 1;
        const int d = c * 128 + wn * 64 + g16 * 16 + e * 8 + (lane & 3) * 2;
        {
            int t = m0 + r0;
            float v0 = oacc[idx][0] * inv0, v1 = oacc[idx][1] * inv0;
            size_t o = ((size_t)t * BB + bb) * FD + hh * DH + d;
            __nv_bfloat16 h0, l0, h1, l1; split2(v0, h0, l0); split2(v1, h1, l1);
            __nv_bfloat162 ph; ph.x = h0; ph.y = h1;
            __nv_bfloat162 pl; pl.x = l0; pl.y = l1;
            *(__nv_bfloat162*)(g_oh + o) = ph;
            *(__nv_bfloat162*)(g_ol + o) = pl;
        }
        {
            int t = m0 + r1;
            float v0 = oacc[idx][2] * inv1, v1 = oacc[idx][3] * inv1;
            size_t o = ((size_t)t * BB + bb) * FD + hh * DH + d;
            __nv_bfloat16 h0, l0, h1, l1; split2(v0, h0, l0); split2(v1, h1, l1);
            __nv_bfloat162 ph; ph.x = h0; ph.y = h1;
            __nv_bfloat162 pl; pl.x = l0; pl.y = l1;
            *(__nv_bfloat162*)(g_oh + o) = ph;
            *(__nv_bfloat162*)(g_ol + o) = pl;
        }
    }
}

// ------------------------------ helper kernels ------------------------------
__global__ __launch_bounds__(256) void split_kernel(
    const float* __restrict__ in, __nv_bfloat16* __restrict__ h,
    __nv_bfloat16* __restrict__ l, int n4)
{
    int i = blockIdx.x * 256 + threadIdx.x;
    if (i >= n4) return;
    float4 v = *(const float4*)(in + (size_t)i * 4);
    __nv_bfloat16 h0,l0,h1,l1,h2,l2,h3,l3;
    split2(v.x,h0,l0); split2(v.y,h1,l1); split2(v.z,h2,l2); split2(v.w,h3,l3);
    __nv_bfloat162 a; a.x=h0; a.y=h1; __nv_bfloat162 b; b.x=h2; b.y=h3;
    __nv_bfloat162 c; c.x=l0; c.y=l1; __nv_bfloat162 d; d.x=l2; d.y=l3;
    *(__nv_bfloat162*)(h + (size_t)i*4)     = a;
    *(__nv_bfloat162*)(h + (size_t)i*4 + 2) = b;
    *(__nv_bfloat162*)(l + (size_t)i*4)     = c;
    *(__nv_bfloat162*)(l + (size_t)i*4 + 2) = d;
}

__global__ __launch_bounds__(256) void split_w_kernel(
    const float* __restrict__ w0, const float* __restrict__ w1,
    const float* __restrict__ w2, const float* __restrict__ w3)
{
    const int which = blockIdx.y;
    const float* in = which == 0 ? w0 : which == 1 ? w1 : which == 2 ? w2 : w3;
    __nv_bfloat16* h = which == 0 ? g_wqh : which == 1 ? g_wkh : which == 2 ? g_wvh : g_woh;
    __nv_bfloat16* l = which == 0 ? g_wql : which == 1 ? g_wkl : which == 2 ? g_wvl : g_wol;
    int i = blockIdx.x * 256 + threadIdx.x;
    if (i >= FD*FD/4) return;
    float4 v = *(const float4*)(in + (size_t)i * 4);
    __nv_bfloat16 a0,b0,a1,b1,a2,b2,a3,b3;
    split2(v.x,a0,b0); split2(v.y,a1,b1); split2(v.z,a2,b2); split2(v.w,a3,b3);
    __nv_bfloat162 p; p.x=a0; p.y=a1; __nv_bfloat162 q; q.x=a2; q.y=a3;
    __nv_bfloat162 r; r.x=b0; r.y=b1; __nv_bfloat162 s; s.x=b2; s.y=b3;
    *(__nv_bfloat162*)(h + (size_t)i*4)     = p;
    *(__nv_bfloat162*)(h + (size_t)i*4 + 2) = q;
    *(__nv_bfloat162*)(l + (size_t)i*4)     = r;
    *(__nv_bfloat162*)(l + (size_t)i*4 + 2) = s;
}

// --------------------------------- launch ----------------------------------
extern "C" void kernel_launch(void* const* d_in, const int* in_sizes, int n_in,
                              void* d_out, int out_size)
{
    const float* x  = (const float*)d_in[0];
    const float* Wq = (const float*)d_in[1];
    const float* bq = (const float*)d_in[2];
    const float* Wk = (const float*)d_in[3];
    const float* bk = (const float*)d_in[4];
    const float* Wv = (const float*)d_in[5];
    const float* bv = (const float*)d_in[6];
    const float* Wo = (const float*)d_in[7];
    const float* bo = (const float*)d_in[8];
    float* out = (float*)d_out;

    cudaFuncSetAttribute(gemm_fused,  cudaFuncAttributeMaxDynamicSharedMemorySize, SMEM_BYTES);
    cudaFuncSetAttribute(attn_kernel, cudaFuncAttributeMaxDynamicSharedMemorySize, ATT_SMEM);

    __nv_bfloat16 *xh, *xl, *oh, *ol;
    cudaGetSymbolAddress((void**)&xh, g_xh);  cudaGetSymbolAddress((void**)&xl, g_xl);
    cudaGetSymbolAddress((void**)&oh, g_oh);  cudaGetSymbolAddress((void**)&ol, g_ol);

    // 0: x split
    split_kernel<<<(MROWS*FD/4 + 255)/256, 256>>>(x, xh, xl, MROWS*FD/4);
    // 1: W splits
    dim3 gW((FD*FD/4 + 255)/256, 4);
    split_w_kernel<<<gW, 256>>>(Wq, Wk, Wv, Wo);
    // 2: fused QKV projection (z = 0,1,2)
    dim3 gQKV(MROWS/BM, FD/BN, 3);
    gemm_fused<<<gQKV, 512, SMEM_BYTES>>>(xh, xl, 0, bq, bk, bv, bo, out);
    // 3: fused flash attention
    dim3 gA(TT/64, NBH);
    attn_kernel<<<gA, 256, ATT_SMEM>>>();
    // 4: output projection (mode 3)
    dim3 gO(MROWS/BM, FD/BN, 1);
    gemm_fused<<<gO, 512, SMEM_BYTES>>>(oh, ol, 3, bq, bk, bv, bo, out);
}

// round 8
// speedup vs baseline: 1.1432x; 1.0025x over previous
#include <cuda_runtime.h>
#include <cuda_bf16.h>
#include <cstdint>

#define TT 2048
#define BB 8
#define FD 768
#define HH 3
#define DH 256
#define MROWS (TT*BB)      // 16384
#define NBH (BB*HH)        // 24

// ------------------------- device scratch (static) -------------------------
__device__ __align__(16) __nv_bfloat16 g_xh[MROWS*FD], g_xl[MROWS*FD];
__device__ __align__(16) __nv_bfloat16 g_wqh[FD*FD], g_wql[FD*FD];
__device__ __align__(16) __nv_bfloat16 g_wkh[FD*FD], g_wkl[FD*FD];
__device__ __align__(16) __nv_bfloat16 g_wvh[FD*FD], g_wvl[FD*FD];
__device__ __align__(16) __nv_bfloat16 g_woh[FD*FD], g_wol[FD*FD];
__device__ __align__(16) __nv_bfloat16 g_qh[NBH*TT*DH], g_ql[NBH*TT*DH];
__device__ __align__(16) __nv_bfloat16 g_kh[NBH*TT*DH], g_kl[NBH*TT*DH];
__device__ __align__(16) __nv_bfloat16 g_vh[NBH*TT*DH], g_vl[NBH*TT*DH];   // (BH,T,D)
__device__ __align__(16) __nv_bfloat16 g_oh[MROWS*FD], g_ol[MROWS*FD];

// ------------------------------ PTX helpers --------------------------------
__device__ __forceinline__ uint32_t smem_u32(const void* p) {
    uint32_t a;
    asm("{ .reg .u64 t; cvta.to.shared.u64 t, %1; cvt.u32.u64 %0, t; }" : "=r"(a) : "l"(p));
    return a;
}
#define CP16(dst, src) \
    asm volatile("cp.async.cg.shared.global [%0], [%1], 16;" :: "r"(dst), "l"(src) : "memory")
#define CP_COMMIT() asm volatile("cp.async.commit_group;" ::: "memory")
#define CP_WAIT1()  asm volatile("cp.async.wait_group 1;" ::: "memory")

#define LDSM4(r0,r1,r2,r3,addr) \
    asm volatile("ldmatrix.sync.aligned.m8n8.x4.shared.b16 {%0,%1,%2,%3}, [%4];" \
        : "=r"(r0), "=r"(r1), "=r"(r2), "=r"(r3) : "r"(addr))
#define LDSM4T(r0,r1,r2,r3,addr) \
    asm volatile("ldmatrix.sync.aligned.m8n8.x4.trans.shared.b16 {%0,%1,%2,%3}, [%4];" \
        : "=r"(r0), "=r"(r1), "=r"(r2), "=r"(r3) : "r"(addr))

#define MMA16816(d, a, b0v, b1v) \
    asm volatile("mma.sync.aligned.m16n8k16.row.col.f32.bf16.bf16.f32 " \
        "{%0,%1,%2,%3}, {%4,%5,%6,%7}, {%8,%9}, {%0,%1,%2,%3};" \
        : "+f"((d)[0]), "+f"((d)[1]), "+f"((d)[2]), "+f"((d)[3]) \
        : "r"((a)[0]), "r"((a)[1]), "r"((a)[2]), "r"((a)[3]), "r"(b0v), "r"(b1v))

#define SWZ(o) ((uint32_t)(o) ^ ((((uint32_t)(o)) >> 3) & 0x70))

__device__ __forceinline__ void split2(float v, __nv_bfloat16& h, __nv_bfloat16& l) {
    h = __float2bfloat16(v);
    l = __float2bfloat16(v - __bfloat162float(h));
}

// ------------- split-bf16 GEMM via mma.sync, 512 threads, 256x128 -----------
#define BM 256
#define BN 128
#define BK 32
#define ROWB 80
#define MAT_A (256*ROWB)
#define MAT_B (128*ROWB)
#define OFF_AH 0
#define OFF_AL MAT_A
#define OFF_BH (2*MAT_A)
#define OFF_BL (2*MAT_A + MAT_B)
#define STAGE_BYTES (2*MAT_A + 2*MAT_B)
#define NSTAGE 3
#define SMEM_BYTES (NSTAGE*STAGE_BYTES)   // 184320

#define QSCALE 0.1803368801111204f    // 0.125 * log2(e)

// mode = blockIdx.z + mode_base: 0=Q, 1=K, 2=V, 3=out-proj
__global__ __launch_bounds__(512, 1) void gemm_fused(
    const __nv_bfloat16* __restrict__ Ah, const __nv_bfloat16* __restrict__ Al,
    int mode_base,
    const float* __restrict__ bq, const float* __restrict__ bk,
    const float* __restrict__ bv, const float* __restrict__ bo,
    float* __restrict__ outF)
{
    extern __shared__ char smem[];
    const uint32_t sb = smem_u32(smem);

    const int tid = threadIdx.x;
    const int wid = tid >> 5, lane = tid & 31;
    const int wm = wid >> 2, wn = wid & 3;
    const int m0 = blockIdx.x * BM, n0 = blockIdx.y * BN;
    const int mode = blockIdx.z + mode_base;

    const __nv_bfloat16* Bh = mode == 0 ? g_wqh : mode == 1 ? g_wkh : mode == 2 ? g_wvh : g_woh;
    const __nv_bfloat16* Bl = mode == 0 ? g_wql : mode == 1 ? g_wkl : mode == 2 ? g_wvl : g_wol;
    const float* bias = mode == 0 ? bq : mode == 1 ? bk : mode == 2 ? bv : bo;
    const int K = FD;

    float acc[4][4][4] = {};

    const int ra0 = tid >> 2,          ca0 = tid & 3;
    const int ra1 = (tid + 512) >> 2,  ca1 = (tid + 512) & 3;
    const int rb  = tid >> 2,          cb  = tid & 3;

    auto load_stage = [&](int kb, int s) {
        const uint32_t st = sb + s * STAGE_BYTES;
        {
            size_t g = (size_t)(m0 + ra0) * K + kb * BK + ca0 * 8;
            uint32_t so = ra0 * ROWB + ca0 * 16;
            CP16(st + OFF_AH + so, Ah + g);
            CP16(st + OFF_AL + so, Al + g);
        }
        {
            size_t g = (size_t)(m0 + ra1) * K + kb * BK + ca1 * 8;
            uint32_t so = ra1 * ROWB + ca1 * 16;
            CP16(st + OFF_AH + so, Ah + g);
            CP16(st + OFF_AL + so, Al + g);
        }
        {
            size_t g = (size_t)(n0 + rb) * K + kb * BK + cb * 8;
            uint32_t so = rb * ROWB + cb * 16;
            CP16(st + OFF_BH + so, Bh + g);
            CP16(st + OFF_BL + so, Bl + g);
        }
    };

    const int NKB = K / BK;
    load_stage(0, 0); CP_COMMIT();
    load_stage(1, 1); CP_COMMIT();

    const int a_row = wm * 64 + (lane & 7) + ((lane >> 3) & 1) * 8;
    const int a_kb  = ((lane >> 4) & 1) * 16;
    const int b_row = wn * 32 + (lane & 7) + (lane >= 16 ? 8 : 0);
    const int b_kb  = ((lane >> 3) & 1) * 16;

    for (int kb = 0; kb < NKB; kb++) {
        CP_WAIT1();
        __syncthreads();
        if (kb + 2 < NKB) load_stage(kb + 2, (kb + 2) % NSTAGE);
        CP_COMMIT();

        const uint32_t st = sb + (kb % NSTAGE) * STAGE_BYTES;
        #pragma unroll
        for (int ks = 0; ks < 2; ks++) {
            uint32_t bhf[2][4], blf[2][4];
            #pragma unroll
            for (int np = 0; np < 2; np++) {
                uint32_t bo2 = (b_row + np * 16) * ROWB + b_kb + ks * 32;
                LDSM4(bhf[np][0], bhf[np][1], bhf[np][2], bhf[np][3], st + OFF_BH + bo2);
                LDSM4(blf[np][0], blf[np][1], blf[np][2], blf[np][3], st + OFF_BL + bo2);
            }
            #pragma unroll
            for (int mf = 0; mf < 4; mf++) {
                uint32_t ah[4], al[4];
                uint32_t ao = (a_row + mf * 16) * ROWB + a_kb + ks * 32;
                LDSM4(ah[0], ah[1], ah[2], ah[3], st + OFF_AH + ao);
                LDSM4(al[0], al[1], al[2], al[3], st + OFF_AL + ao);
                // term-major: same-acc reuse distance 4
                #pragma unroll
                for (int np = 0; np < 2; np++) {
                    MMA16816(acc[mf][np*2],   ah, bhf[np][0], bhf[np][1]);
                    MMA16816(acc[mf][np*2+1], ah, bhf[np][2], bhf[np][3]);
                }
                #pragma unroll
                for (int np = 0; np < 2; np++) {
                    MMA16816(acc[mf][np*2],   ah, blf[np][0], blf[np][1]);
                    MMA16816(acc[mf][np*2+1], ah, blf[np][2], blf[np][3]);
                }
                #pragma unroll
                for (int np = 0; np < 2; np++) {
                    MMA16816(acc[mf][np*2],   al, bhf[np][0], bhf[np][1]);
                    MMA16816(acc[mf][np*2+1], al, bhf[np][2], bhf[np][3]);
                }
            }
        }
        __syncthreads();
    }

    const int mrow = m0 + wm * 64 + (lane >> 2);
    const int ncol = n0 + wn * 32 + (lane & 3) * 2;
    const float oscale = (mode == 0) ? QSCALE : 1.0f;

    #pragma unroll
    for (int mf = 0; mf < 4; mf++) {
        #pragma unroll
        for (int half = 0; half < 2; half++) {
            const int m = mrow + mf * 16 + half * 8;
            #pragma unroll
            for (int nf = 0; nf < 4; nf++) {
                const int n = ncol + nf * 8;
                float v0 = (acc[mf][nf][half * 2]     + __ldg(&bias[n]))     * oscale;
                float v1 = (acc[mf][nf][half * 2 + 1] + __ldg(&bias[n + 1])) * oscale;

                if (mode <= 2) {           // Q/K/V: (BH,T,D) hi/lo, coalesced
                    __nv_bfloat16* oH = mode == 0 ? g_qh : mode == 1 ? g_kh : g_vh;
                    __nv_bfloat16* oL = mode == 0 ? g_ql : mode == 1 ? g_kl : g_vl;
                    const int t = m >> 3, b = m & 7, h = n >> 8, d = n & 255;
                    size_t o = ((size_t)(b * HH + h) * TT + t) * DH + d;
                    __nv_bfloat16 h0, l0, h1, l1; split2(v0, h0, l0); split2(v1, h1, l1);
                    __nv_bfloat162 ph; ph.x = h0; ph.y = h1;
                    __nv_bfloat162 pl; pl.x = l0; pl.y = l1;
                    *(__nv_bfloat162*)(oH + o) = ph;
                    *(__nv_bfloat162*)(oL + o) = pl;
                } else {                   // out projection: fp32 (T*B, F)
                    size_t o = (size_t)m * FD + n;
                    float2 f; f.x = v0; f.y = v1;
                    *(float2*)(outF + o) = f;
                }
            }
        }
    }
}

// --------------------------- fused flash attention --------------------------
// CTA: 64 q-rows of one bh; 16 kv-tiles of 128 t. 256 threads (4m x 2n warps).
// Two 64KB ping-pong buffers hold [128 t][128 d] hi/lo chunks (K or V).
#define QMAT 8192
#define Q_OFF 0
#define B0_OFF 65536
#define B1_OFF 131072
#define P_OFF 196608
#define RMAX_OFF 229376
#define RSUM_OFF 229888
#define ATT_SMEM 230400
#define NKV (TT/128)    // 16

__global__ __launch_bounds__(256, 1) void attn_kernel()
{
    extern __shared__ char sm[];
    const uint32_t sb = smem_u32(sm);
    const int tid = threadIdx.x, lane = tid & 31, wid = tid >> 5;
    const int wm = wid & 3, wn = wid >> 2;             // 4 x 2
    const int bh = blockIdx.y, m0 = blockIdx.x * 64;

    auto load_kv = [&](const __nv_bfloat16* __restrict__ srcH,
                       const __nv_bfloat16* __restrict__ srcL,
                       int tile, int c, uint32_t bufoff) {
        #pragma unroll
        for (int dh = 0; dh < 2; dh++) {
            #pragma unroll
            for (int i = 0; i < 4; i++) {
                int ci = tid + i * 256;
                int r = ci >> 3, cc = ci & 7;
                size_t g = ((size_t)bh * TT + tile * 128 + r) * DH + c * 128 + dh * 64 + cc * 8;
                uint32_t so = SWZ(r * 128 + cc * 16);
                CP16(sb + bufoff + dh * 32768 + so,         srcH + g);
                CP16(sb + bufoff + dh * 32768 + 16384 + so, srcL + g);
            }
        }
    };

    #pragma unroll
    for (int i = 0; i < 16; i++) {
        int ci = tid + i * 256;
        int mat = ci >> 9, w = ci & 511, r = w >> 3, c = w & 7;
        int j = mat >> 1, hl = mat & 1;
        size_t g = ((size_t)bh * TT + m0 + r) * DH + j * 64 + c * 8;
        const __nv_bfloat16* src = hl ? g_ql : g_qh;
        CP16(sb + Q_OFF + mat * QMAT + SWZ(r * 128 + c * 16), src + g);
    }
    load_kv(g_kh, g_kl, 0, 0, B0_OFF); CP_COMMIT();
    load_kv(g_kh, g_kl, 0, 1, B1_OFF); CP_COMMIT();

    const int a_rl = (lane & 7) + ((lane >> 3) & 1) * 8;
    const int a_kb = ((lane >> 4) & 1) * 16;
    const int b_rl = (lane & 7) + (lane >= 16 ? 8 : 0);
    const int b_kb = ((lane >> 3) & 1) * 16;
    const int v_rl = (lane & 7) + ((lane >> 3) & 1) * 8;
    const int v_cb = ((lane >> 4) & 1) * 16;

    float oacc[16][4] = {};
    float sacc[8][4];
    float mrun0 = -1e30f, mrun1 = -1e30f, lrun0 = 0.f, lrun1 = 0.f;
    const int r0 = wm * 16 + (lane >> 2), r1 = r0 + 8;
    float* rmax = (float*)(sm + RMAX_OFF);
    float* rsum = (float*)(sm + RSUM_OFF);

    for (int tile = 0; tile < NKV; tile++) {
        #pragma unroll
        for (int f = 0; f < 8; f++) { sacc[f][0]=0.f; sacc[f][1]=0.f; sacc[f][2]=0.f; sacc[f][3]=0.f; }

        // ---- QK: 2 phases over d-halves ----
        #pragma unroll
        for (int c = 0; c < 2; c++) {
            CP_WAIT1(); __syncthreads();
            const uint32_t kb_buf = sb + (c ? B1_OFF : B0_OFF);
            #pragma unroll
            for (int ks = 0; ks < 8; ks++) {
                const uint32_t qm = sb + Q_OFF + (c * 2 + (ks >> 2)) * 16384;
                const uint32_t km = kb_buf + (ks >> 2) * 32768;
                uint32_t ao = SWZ((wm * 16 + a_rl) * 128 + (ks & 3) * 32 + a_kb);
                uint32_t qh[4], ql[4];
                LDSM4(qh[0], qh[1], qh[2], qh[3], qm + ao);
                LDSM4(ql[0], ql[1], ql[2], ql[3], qm + 8192 + ao);
                // g16 in pairs: term-major, same-acc reuse distance 4
                #pragma unroll
                for (int gp = 0; gp < 2; gp++) {
                    uint32_t kh[2][4], kl[2][4];
                    #pragma unroll
                    for (int gi = 0; gi < 2; gi++) {
                        const int g16 = gp * 2 + gi;
                        uint32_t bo = SWZ((wn * 64 + g16 * 16 + b_rl) * 128 + (ks & 3) * 32 + b_kb);
                        LDSM4(kh[gi][0], kh[gi][1], kh[gi][2], kh[gi][3], km + bo);
                        LDSM4(kl[gi][0], kl[gi][1], kl[gi][2], kl[gi][3], km + 16384 + bo);
                    }
                    #pragma unroll
                    for (int gi = 0; gi < 2; gi++) {
                        const int f = (gp * 2 + gi) * 2;
                        MMA16816(sacc[f],   qh, kh[gi][0], kh[gi][1]);
                        MMA16816(sacc[f+1], qh, kh[gi][2], kh[gi][3]);
                    }
                    #pragma unroll
                    for (int gi = 0; gi < 2; gi++) {
                        const int f = (gp * 2 + gi) * 2;
                        MMA16816(sacc[f],   qh, kl[gi][0], kl[gi][1]);
                        MMA16816(sacc[f+1], qh, kl[gi][2], kl[gi][3]);
                    }
                    #pragma unroll
                    for (int gi = 0; gi < 2; gi++) {
                        const int f = (gp * 2 + gi) * 2;
                        MMA16816(sacc[f],   ql, kh[gi][0], kh[gi][1]);
                        MMA16816(sacc[f+1], ql, kh[gi][2], kh[gi][3]);
                    }
                }
            }
            __syncthreads();
            load_kv(g_vh, g_vl, tile, c, c ? B1_OFF : B0_OFF);
            CP_COMMIT();
        }

        // ---- online softmax (scores in log2 units via folded QSCALE) ----
        float mx0 = -1e30f, mx1 = -1e30f;
        #pragma unroll
        for (int f = 0; f < 8; f++) {
            mx0 = fmaxf(mx0, fmaxf(sacc[f][0], sacc[f][1]));
            mx1 = fmaxf(mx1, fmaxf(sacc[f][2], sacc[f][3]));
        }
        mx0 = fmaxf(mx0, __shfl_xor_sync(0xffffffffu, mx0, 1));
        mx0 = fmaxf(mx0, __shfl_xor_sync(0xffffffffu, mx0, 2));
        mx1 = fmaxf(mx1, __shfl_xor_sync(0xffffffffu, mx1, 1));
        mx1 = fmaxf(mx1, __shfl_xor_sync(0xffffffffu, mx1, 2));
        if ((lane & 3) == 0) { rmax[wn * 64 + r0] = mx0; rmax[wn * 64 + r1] = mx1; }
        __syncthreads();

        float mn0 = fmaxf(mrun0, fmaxf(rmax[r0], rmax[64 + r0]));
        float mn1 = fmaxf(mrun1, fmaxf(rmax[r1], rmax[64 + r1]));
        float a0 = exp2f(mrun0 - mn0), a1 = exp2f(mrun1 - mn1);
        mrun0 = mn0; mrun1 = mn1;

        float s0 = 0.f, s1 = 0.f;
        #pragma unroll
        for (int f = 0; f < 8; f++) {
            sacc[f][0] = exp2f(sacc[f][0] - mn0);
            sacc[f][1] = exp2f(sacc[f][1] - mn0);
            sacc[f][2] = exp2f(sacc[f][2] - mn1);
            sacc[f][3] = exp2f(sacc[f][3] - mn1);
            s0 += sacc[f][0] + sacc[f][1];
            s1 += sacc[f][2] + sacc[f][3];
        }
        s0 += __shfl_xor_sync(0xffffffffu, s0, 1);
        s0 += __shfl_xor_sync(0xffffffffu, s0, 2);
        s1 += __shfl_xor_sync(0xffffffffu, s1, 1);
        s1 += __shfl_xor_sync(0xffffffffu, s1, 2);
        if ((lane & 3) == 0) { rsum[wn * 64 + r0] = s0; rsum[wn * 64 + r1] = s1; }

        #pragma unroll
        for (int f = 0; f < 16; f++) {
            oacc[f][0] *= a0; oacc[f][1] *= a0;
            oacc[f][2] *= a1; oacc[f][3] *= a1;
        }

        // P -> smem
        {
            const uint32_t pmo = P_OFF + wn * 16384;
            #pragma unroll
            for (int f = 0; f < 8; f++) {
                int cl = f * 8 + (lane & 3) * 2;
                __nv_bfloat16 h0, l0, h1, l1;
                split2(sacc[f][0], h0, l0); split2(sacc[f][1], h1, l1);
                __nv_bfloat162 ph; ph.x = h0; ph.y = h1;
                __nv_bfloat162 pl; pl.x = l0; pl.y = l1;
                uint32_t off = SWZ(r0 * 128 + cl * 2);
                *(__nv_bfloat162*)(sm + pmo + off)        = ph;
                *(__nv_bfloat162*)(sm + pmo + 8192 + off) = pl;
                split2(sacc[f][2], h0, l0); split2(sacc[f][3], h1, l1);
                ph.x = h0; ph.y = h1; pl.x = l0; pl.y = l1;
                off = SWZ(r1 * 128 + cl * 2);
                *(__nv_bfloat162*)(sm + pmo + off)        = ph;
                *(__nv_bfloat162*)(sm + pmo + 8192 + off) = pl;
            }
        }
        __syncthreads();

        lrun0 = lrun0 * a0 + rsum[r0] + rsum[64 + r0];
        lrun1 = lrun1 * a1 + rsum[r1] + rsum[64 + r1];

        // ---- AV: 2 phases over d-halves (V via ldmatrix.trans) ----
        #pragma unroll
        for (int c = 0; c < 2; c++) {
            CP_WAIT1(); __syncthreads();
            const uint32_t v_buf = sb + (c ? B1_OFF : B0_OFF) + wn * 32768;  // dhalf = wn
            #pragma unroll
            for (int ks = 0; ks < 8; ks++) {
                const uint32_t pm = sb + P_OFF + (ks >> 2) * 16384;
                uint32_t ao = SWZ((wm * 16 + a_rl) * 128 + (ks & 3) * 32 + a_kb);
                uint32_t ph[4], pl[4];
                LDSM4(ph[0], ph[1], ph[2], ph[3], pm + ao);
                LDSM4(pl[0], pl[1], pl[2], pl[3], pm + 8192 + ao);
                const uint32_t vrow = ks * 16 + v_rl;
                #pragma unroll
                for (int gp = 0; gp < 2; gp++) {
                    uint32_t vh[2][4], vl[2][4];
                    #pragma unroll
                    for (int gi = 0; gi < 2; gi++) {
                        const int g16 = gp * 2 + gi;
                        uint32_t bo = SWZ(vrow * 128 + g16 * 32 + v_cb);
                        LDSM4T(vh[gi][0], vh[gi][1], vh[gi][2], vh[gi][3], v_buf + bo);
                        LDSM4T(vl[gi][0], vl[gi][1], vl[gi][2], vl[gi][3], v_buf + 16384 + bo);
                    }
                    #pragma unroll
                    for (int gi = 0; gi < 2; gi++) {
                        const int f = c * 8 + (gp * 2 + gi) * 2;
                        MMA16816(oacc[f],   ph, vh[gi][0], vh[gi][1]);
                        MMA16816(oacc[f+1], ph, vh[gi][2], vh[gi][3]);
                    }
                    #pragma unroll
                    for (int gi = 0; gi < 2; gi++) {
                        const int f = c * 8 + (gp * 2 + gi) * 2;
                        MMA16816(oacc[f],   ph, vl[gi][0], vl[gi][1]);
                        MMA16816(oacc[f+1], ph, vl[gi][2], vl[gi][3]);
                    }
                    #pragma unroll
                    for (int gi = 0; gi < 2; gi++) {
                        const int f = c * 8 + (gp * 2 + gi) * 2;
                        MMA16816(oacc[f],   pl, vh[gi][0], vh[gi][1]);
                        MMA16816(oacc[f+1], pl, vh[gi][2], vh[gi][3]);
                    }
                }
            }
            __syncthreads();
            if (tile + 1 < NKV) load_kv(g_kh, g_kl, tile + 1, c, c ? B1_OFF : B0_OFF);
            CP_COMMIT();
        }
    }

    // ---- epilogue: normalize + write hi/lo for output projection ----
    const int bb = bh / HH, hh = bh % HH;
    const float inv0 = 1.f / lrun0, inv1 = 1.f / lrun1;
    #pragma unroll
    for (int idx = 0; idx < 16; idx++) {
        const int c = idx >> 3, g16 = (idx & 7) >> 1, e = idx & 1;
        const int d = c * 128 + wn * 64 + g16 * 16 + e * 8 + (lane & 3) * 2;
        {
            int t = m0 + r0;
            float v0 = oacc[idx][0] * inv0, v1 = oacc[idx][1] * inv0;
            size_t o = ((size_t)t * BB + bb) * FD + hh * DH + d;
            __nv_bfloat16 h0, l0, h1, l1; split2(v0, h0, l0); split2(v1, h1, l1);
            __nv_bfloat162 ph; ph.x = h0; ph.y = h1;
            __nv_bfloat162 pl; pl.x = l0; pl.y = l1;
            *(__nv_bfloat162*)(g_oh + o) = ph;
            *(__nv_bfloat162*)(g_ol + o) = pl;
        }
        {
            int t = m0 + r1;
            float v0 = oacc[idx][2] * inv1, v1 = oacc[idx][3] * inv1;
            size_t o = ((size_t)t * BB + bb) * FD + hh * DH + d;
            __nv_bfloat16 h0, l0, h1, l1; split2(v0, h0, l0); split2(v1, h1, l1);
            __nv_bfloat162 ph; ph.x = h0; ph.y = h1;
            __nv_bfloat162 pl; pl.x = l0; pl.y = l1;
            *(__nv_bfloat162*)(g_oh + o) = ph;
            *(__nv_bfloat162*)(g_ol + o) = pl;
        }
    }
}

// ------------------------------ helper kernels ------------------------------
__global__ __launch_bounds__(256) void split_kernel(
    const float* __restrict__ in, __nv_bfloat16* __restrict__ h,
    __nv_bfloat16* __restrict__ l, int n4)
{
    int i = blockIdx.x * 256 + threadIdx.x;
    if (i >= n4) return;
    float4 v = *(const float4*)(in + (size_t)i * 4);
    __nv_bfloat16 h0,l0,h1,l1,h2,l2,h3,l3;
    split2(v.x,h0,l0); split2(v.y,h1,l1); split2(v.z,h2,l2); split2(v.w,h3,l3);
    __nv_bfloat162 a; a.x=h0; a.y=h1; __nv_bfloat162 b; b.x=h2; b.y=h3;
    __nv_bfloat162 c; c.x=l0; c.y=l1; __nv_bfloat162 d; d.x=l2; d.y=l3;
    *(__nv_bfloat162*)(h + (size_t)i*4)     = a;
    *(__nv_bfloat162*)(h + (size_t)i*4 + 2) = b;
    *(__nv_bfloat162*)(l + (size_t)i*4)     = c;
    *(__nv_bfloat162*)(l + (size_t)i*4 + 2) = d;
}

__global__ __launch_bounds__(256) void split_w_kernel(
    const float* __restrict__ w0, const float* __restrict__ w1,
    const float* __restrict__ w2, const float* __restrict__ w3)
{
    const int which = blockIdx.y;
    const float* in = which == 0 ? w0 : which == 1 ? w1 : which == 2 ? w2 : w3;
    __nv_bfloat16* h = which == 0 ? g_wqh : which == 1 ? g_wkh : which == 2 ? g_wvh : g_woh;
    __nv_bfloat16* l = which == 0 ? g_wql : which == 1 ? g_wkl : which == 2 ? g_wvl : g_wol;
    int i = blockIdx.x * 256 + threadIdx.x;
    if (i >= FD*FD/4) return;
    float4 v = *(const float4*)(in + (size_t)i * 4);
    __nv_bfloat16 a0,b0,a1,b1,a2,b2,a3,b3;
    split2(v.x,a0,b0); split2(v.y,a1,b1); split2(v.z,a2,b2); split2(v.w,a3,b3);
    __nv_bfloat162 p; p.x=a0; p.y=a1; __nv_bfloat162 q; q.x=a2; q.y=a3;
    __nv_bfloat162 r; r.x=b0; r.y=b1; __nv_bfloat162 s; s.x=b2; s.y=b3;
    *(__nv_bfloat162*)(h + (size_t)i*4)     = p;
    *(__nv_bfloat162*)(h + (size_t)i*4 + 2) = q;
    *(__nv_bfloat162*)(l + (size_t)i*4)     = r;
    *(__nv_bfloat162*)(l + (size_t)i*4 + 2) = s;
}

// --------------------------------- launch ----------------------------------
extern "C" void kernel_launch(void* const* d_in, const int* in_sizes, int n_in,
                              void* d_out, int out_size)
{
    const float* x  = (const float*)d_in[0];
    const float* Wq = (const float*)d_in[1];
    const float* bq = (const float*)d_in[2];
    const float* Wk = (const float*)d_in[3];
    const float* bk = (const float*)d_in[4];
    const float* Wv = (const float*)d_in[5];
    const float* bv = (const float*)d_in[6];
    const float* Wo = (const float*)d_in[7];
    const float* bo = (const float*)d_in[8];
    float* out = (float*)d_out;

    cudaFuncSetAttribute(gemm_fused,  cudaFuncAttributeMaxDynamicSharedMemorySize, SMEM_BYTES);
    cudaFuncSetAttribute(attn_kernel, cudaFuncAttributeMaxDynamicSharedMemorySize, ATT_SMEM);

    __nv_bfloat16 *xh, *xl, *oh, *ol;
    cudaGetSymbolAddress((void**)&xh, g_xh);  cudaGetSymbolAddress((void**)&xl, g_xl);
    cudaGetSymbolAddress((void**)&oh, g_oh);  cudaGetSymbolAddress((void**)&ol, g_ol);

    // 0: x split
    split_kernel<<<(MROWS*FD/4 + 255)/256, 256>>>(x, xh, xl, MROWS*FD/4);
    // 1: W splits
    dim3 gW((FD*FD/4 + 255)/256, 4);
    split_w_kernel<<<gW, 256>>>(Wq, Wk, Wv, Wo);
    // 2: fused QKV projection (z = 0,1,2)
    dim3 gQKV(MROWS/BM, FD/BN, 3);
    gemm_fused<<<gQKV, 512, SMEM_BYTES>>>(xh, xl, 0, bq, bk, bv, bo, out);
    // 3: fused flash attention
    dim3 gA(TT/64, NBH);
    attn_kernel<<<gA, 256, ATT_SMEM>>>();
    // 4: output projection (mode 3)
    dim3 gO(MROWS/BM, FD/BN, 1);
    gemm_fused<<<gO, 512, SMEM_BYTES>>>(oh, ol, 3, bq, bk, bv, bo, out);
}